// round 2
// baseline (speedup 1.0000x reference)
#include <cuda_runtime.h>
#include <cstdint>

// Problem constants
#define NVOX   65536          // B*W*H*L = 2*32*32*32
#define DDIM   512
#define EHEADS 64
#define VOUT   16
#define NBLOCKS 256
#define TILE_M 128            // voxels per compute CTA
#define MAX_TILES 576         // ceil((NVOX + 64*127)/TILE_M) bound
#define IDXBUF 73728          // padded index buffer capacity

// ---------------- scratch (device globals: no allocations allowed) ----------
__device__ int g_counts[EHEADS];
__device__ int g_cursor[EHEADS];
__device__ int g_idx[IDXBUF];
__device__ int g_tile_head[640];

// ---------------- f32x2 helpers (sm_103a packed fp32) ------------------------
__device__ __forceinline__ void fma2(unsigned long long& d,
                                     unsigned long long a,
                                     unsigned long long b) {
    asm("fma.rn.f32x2 %0, %1, %2, %0;" : "+l"(d) : "l"(a), "l"(b));
}
__device__ __forceinline__ unsigned long long pack2(float a, float b) {
    unsigned long long r;
    asm("mov.b64 %0, {%1, %2};" : "=l"(r) : "f"(a), "f"(b));
    return r;
}
__device__ __forceinline__ float unpack_sum(unsigned long long a) {
    float lo, hi;
    asm("mov.b64 {%0, %1}, %2;" : "=f"(lo), "=f"(hi) : "l"(a));
    return lo + hi;
}

// ---------------- K0: zero counts -------------------------------------------
__global__ void k0_zero() {
    if (threadIdx.x < EHEADS) g_counts[threadIdx.x] = 0;
}

// ---------------- K1: per-head histogram ------------------------------------
__global__ void k1_count(const int* __restrict__ btg,
                         const int* __restrict__ b2h) {
    __shared__ int bh_s[NBLOCKS];
    __shared__ int hist[EHEADS];
    int tid = threadIdx.x;
    bh_s[tid] = b2h[tid];                 // 256 threads, 256 entries
    if (tid < EHEADS) hist[tid] = 0;
    __syncthreads();
    int base = blockIdx.x * 1024;
#pragma unroll
    for (int k = 0; k < 4; ++k) {
        int n = base + k * 256 + tid;
        atomicAdd(&hist[bh_s[btg[n]]], 1);
    }
    __syncthreads();
    if (tid < EHEADS) atomicAdd(&g_counts[tid], hist[tid]);
}

// ---------------- K2: padded scan, cursors, tile map, pad fill ---------------
__global__ void k2_scan() {
    __shared__ int cnts[EHEADS];
    __shared__ int poff[EHEADS + 1];
    int tid = threadIdx.x;                // 128 threads
    if (tid < EHEADS) cnts[tid] = g_counts[tid];
    __syncthreads();
    if (tid == 0) {
        int run = 0;
        for (int h = 0; h < EHEADS; ++h) {
            poff[h] = run;
            run += ((cnts[h] + TILE_M - 1) / TILE_M) * TILE_M;
        }
        poff[EHEADS] = run;
    }
    __syncthreads();
    // init all tile heads to -1
    for (int t = tid; t < 640; t += 128) g_tile_head[t] = -1;
    __syncthreads();
    if (tid < EHEADS) {
        int h = tid;
        int start = poff[h];
        int end = poff[h + 1];
        g_cursor[h] = start;
        for (int t = start / TILE_M; t < end / TILE_M; ++t) g_tile_head[t] = h;
        for (int p = start + cnts[h]; p < end; ++p) g_idx[p] = -1;
    }
}

// ---------------- K3: scatter voxel indices into head buckets ----------------
__global__ void k3_scatter(const int* __restrict__ btg,
                           const int* __restrict__ b2h) {
    __shared__ int bh_s[NBLOCKS];
    __shared__ int cnt[EHEADS];
    __shared__ int base_s[EHEADS];
    int tid = threadIdx.x;
    bh_s[tid] = b2h[tid];
    if (tid < EHEADS) cnt[tid] = 0;
    __syncthreads();
    int base = blockIdx.x * 1024;
    int h[4], r[4];
#pragma unroll
    for (int k = 0; k < 4; ++k) {
        int n = base + k * 256 + tid;
        h[k] = bh_s[btg[n]];
        r[k] = atomicAdd(&cnt[h[k]], 1);
    }
    __syncthreads();
    if (tid < EHEADS) base_s[tid] = atomicAdd(&g_cursor[tid], cnt[tid]);
    __syncthreads();
#pragma unroll
    for (int k = 0; k < 4; ++k) {
        int n = base + k * 256 + tid;
        g_idx[base_s[h[k]] + r[k]] = n;
    }
}

// ---------------- K4: grouped head-GEMV, lane-per-voxel, f32x2 ---------------
__global__ __launch_bounds__(TILE_M, 4)
void k4_compute(const float* __restrict__ x,
                const float* __restrict__ Wh,
                const float* __restrict__ bh,
                float* __restrict__ out) {
    __shared__ __align__(16) float Ws[VOUT * DDIM];   // 32 KB, [v][d]
    __shared__ float bs[VOUT];

    int t = blockIdx.x;
    int head = g_tile_head[t];
    if (head < 0) return;

    // stage W[head] (contiguous 8192 floats) and bias into smem
    {
        const float4* src = (const float4*)(Wh + head * (VOUT * DDIM));
        float4* dst = (float4*)Ws;
#pragma unroll
        for (int i = 0; i < 16; ++i)
            dst[threadIdx.x + TILE_M * i] = src[threadIdx.x + TILE_M * i];
        if (threadIdx.x < VOUT) bs[threadIdx.x] = bh[head * VOUT + threadIdx.x];
    }
    __syncthreads();

    int pos = t * TILE_M + threadIdx.x;
    int vox = g_idx[pos];
    bool valid = vox >= 0;
    int voxc = valid ? vox : 0;           // padded lanes compute garbage, skip store

    const float4* xrow = (const float4*)x + (size_t)voxc * (DDIM / 4);
    const ulonglong2* Ws2 = (const ulonglong2*)Ws;  // 4 floats = 2 f32x2 pairs

    unsigned long long acc[VOUT];
#pragma unroll
    for (int v = 0; v < VOUT; ++v) acc[v] = 0ull;

#pragma unroll 1
    for (int line = 0; line < 16; ++line) {          // 128B of x per iter
        float4 xv[8];
#pragma unroll
        for (int j = 0; j < 8; ++j) xv[j] = xrow[line * 8 + j];
#pragma unroll
        for (int j = 0; j < 8; ++j) {
            unsigned long long xa = pack2(xv[j].x, xv[j].y);
            unsigned long long xb = pack2(xv[j].z, xv[j].w);
            int wbase = line * 8 + j;                // ulonglong2 index within a v-row
#pragma unroll
            for (int v = 0; v < VOUT; ++v) {
                ulonglong2 w = Ws2[v * (DDIM / 4) + wbase];  // broadcast LDS.128
                fma2(acc[v], xa, w.x);
                fma2(acc[v], xb, w.y);
            }
        }
    }

    if (valid) {
        float4* orow = (float4*)(out + (size_t)vox * VOUT);
#pragma unroll
        for (int q = 0; q < 4; ++q) {
            float4 r;
            r.x = unpack_sum(acc[q * 4 + 0]) + bs[q * 4 + 0];
            r.y = unpack_sum(acc[q * 4 + 1]) + bs[q * 4 + 1];
            r.z = unpack_sum(acc[q * 4 + 2]) + bs[q * 4 + 2];
            r.w = unpack_sum(acc[q * 4 + 3]) + bs[q * 4 + 3];
            orow[q] = r;
        }
    }
}

// ---------------- launch ------------------------------------------------------
extern "C" void kernel_launch(void* const* d_in, const int* in_sizes, int n_in,
                              void* d_out, int out_size) {
    const int*   btg = (const int*)d_in[0];     // block_type_grid (65536)
    const float* x   = (const float*)d_in[1];   // x (65536*512)
    const float* Wh  = (const float*)d_in[2];   // W_heads (64*16*512)
    const float* bh  = (const float*)d_in[3];   // b_heads (64*16)
    const int*   b2h = (const int*)d_in[4];     // block2head (256)
    float* out = (float*)d_out;

    k0_zero<<<1, 64>>>();
    k1_count<<<64, 256>>>(btg, b2h);
    k2_scan<<<1, 128>>>();
    k3_scatter<<<64, 256>>>(btg, b2h);
    k4_compute<<<MAX_TILES, TILE_M>>>(x, Wh, bh, out);
}